// round 15
// baseline (speedup 1.0000x reference)
#include <cuda_runtime.h>
#include <math.h>

#define R_ 3
#define T_ 3
#define N_ 50000
#define OPS_ 24
#define E_ 400000
#define B_ 32
#define MAXDEG_ 8
#define QD_ 128
#define H_ 128

// ---------------- device scratch ----------------
__device__ float g_xgI[2 * 25 * 512];
__device__ float g_Wt[2 * 128 * 512];
__device__ unsigned g_Wb[2 * 64 * 512];
__device__ unsigned g_hclsP[2 * 625 * 64];
__device__ float g_ccls[2 * 625 * 128];
__device__ float g_eh[N_ * 256];
__device__ float g_attn[N_ * OPS_];
__device__ float g_qWihT[6 * 128 * 512];
__device__ float g_qWhhT[6 * 128 * 512];
__device__ float g_qys[R_ * 2 * T_ * B_ * H_];
__device__ float g_qaT[R_ * T_ * (OPS_ + 1) * B_];
__device__ float g_memA[N_ * B_];
__device__ float g_memB[N_ * B_];
__device__ float g_sums[R_ * T_ * B_];
__device__ int g_deg[N_];
__device__ int g_rowptr[N_ + 1];
__device__ int g_cursor[N_];
__device__ int2 g_csr2[2 * E_];

__device__ __forceinline__ float sigm(float x) { return 1.f / (1.f + expf(-x)); }
__device__ __forceinline__ float tanh_fast(float x) {
    float y; asm("tanh.approx.f32 %0, %1;" : "=f"(y) : "f"(x)); return y;
}
__device__ __forceinline__ float sigm_fast(float x) { return 0.5f + 0.5f * tanh_fast(0.5f * x); }
__device__ __forceinline__ unsigned f2tf32(float x) {
    unsigned y; asm("cvt.rna.tf32.f32 %0, %1;" : "=r"(y) : "f"(x)); return y;
}
__device__ __forceinline__ unsigned packbf(float lo, float hi) {
    unsigned r; asm("cvt.rn.bf16x2.f32 %0, %1, %2;" : "=r"(r) : "f"(hi), "f"(lo)); return r;
}
__device__ __forceinline__ unsigned short bf16of(float x) {
    unsigned short h; asm("cvt.rn.bf16.f32 %0, %1;" : "=h"(h) : "f"(x)); return h;
}
__device__ __forceinline__ void mma16(float* c, unsigned a0, unsigned a1, unsigned a2,
                                      unsigned a3, unsigned b0, unsigned b1) {
    asm volatile("mma.sync.aligned.m16n8k16.row.col.f32.bf16.bf16.f32 "
                 "{%0,%1,%2,%3},{%4,%5,%6,%7},{%8,%9},{%0,%1,%2,%3};"
                 : "+f"(c[0]), "+f"(c[1]), "+f"(c[2]), "+f"(c[3])
                 : "r"(a0), "r"(a1), "r"(a2), "r"(a3), "r"(b0), "r"(b1));
}

// ---------------- precompute ----------------
__global__ void k_xg(const float* __restrict__ ent_emb, const float* __restrict__ e_Wih,
                     const float* __restrict__ e_bih, const float* __restrict__ e_bhh) {
    int d = blockIdx.x, dir = blockIdx.y, tid = threadIdx.x;
    int j = tid >> 2, g = tid & 3;
    int row = g * 128 + j;
    const float* w = e_Wih + (dir * 512 + row) * 128;
    const float* x = ent_emb + d * 128;
    float s = e_bih[dir * 512 + row] + e_bhh[dir * 512 + row];
    for (int k = 0; k < 128; k++) s += x[k] * w[k];
    g_xgI[(dir * 25 + d) * 512 + tid] = s;
}

__global__ void k_whhT(const float* __restrict__ e_Whh) {
    int k = blockIdx.x, dir = blockIdx.y, tid = threadIdx.x;
    int j = tid >> 2, g = tid & 3;
    float v = e_Whh[(dir * 512 + g * 128 + j) * 128 + k];
    g_Wt[(dir * 128 + k) * 512 + tid] = __uint_as_float(f2tf32(v));
}

__global__ void k_wpack() {
    int i = blockIdx.x * 512 + threadIdx.x;
    if (i < 65536) {
        int dir = i >> 15, rem = i & 32767, k2 = rem >> 9, col = rem & 511;
        float lo = g_Wt[(dir * 128 + 2 * k2) * 512 + col];
        float hi = g_Wt[(dir * 128 + 2 * k2 + 1) * 512 + col];
        g_Wb[dir * 32768 + k2 * 512 + col] = packbf(lo, hi);
    }
}

// ---------------- class table: steps 0..1 for 625 prefixes ----------------
__global__ void k_cls() {
    __shared__ float sw[16 * 516];
    __shared__ float sh0[8][128];
    int tid = threadIdx.x, warp = tid >> 5, lane = tid & 31;
    int cls = blockIdx.x * 8 + warp;
    int dir = blockIdx.y;
    bool active = (cls < 625);
    int d0 = 0, d1 = 0;
    if (active) { d0 = cls / 25; d1 = cls - d0 * 25; }
    const float* xg0 = g_xgI + (dir * 25 + d0) * 512;
    const float* xg1 = g_xgI + (dir * 25 + d1) * 512;
    const float* Wt = g_Wt + dir * 128 * 512;

    float c0[4];
    float ax[4], ay[4], az[4], aw[4];
    if (active) {
#pragma unroll
        for (int q = 0; q < 4; q++) {
            int u = lane + 32 * q;
            float4 xv = *(const float4*)&xg0[u * 4];
            c0[q] = sigm_fast(xv.x) * tanh_fast(xv.z);
            float h0 = sigm_fast(xv.w) * tanh_fast(c0[q]);
            sh0[warp][u] = __uint_as_float(f2tf32(h0));
            float4 a1 = *(const float4*)&xg1[u * 4];
            ax[q] = a1.x; ay[q] = a1.y; az[q] = a1.z; aw[q] = a1.w;
        }
    }
    for (int ch = 0; ch < 8; ch++) {
        __syncthreads();
#pragma unroll
        for (int q = 0; q < 8; q++) {
            int i = tid + q * 256;
            int r = i >> 7, c4 = i & 127;
            *(float4*)&sw[r * 516 + c4 * 4] = *(const float4*)&Wt[(ch * 16 + r) * 512 + c4 * 4];
        }
        __syncthreads();
        if (active) {
#pragma unroll
            for (int kk = 0; kk < 16; kk++) {
                float hk = sh0[warp][ch * 16 + kk];
#pragma unroll
                for (int q = 0; q < 4; q++) {
                    float4 w4 = *(const float4*)&sw[kk * 516 + (lane + 32 * q) * 4];
                    ax[q] += hk * w4.x; ay[q] += hk * w4.y;
                    az[q] += hk * w4.z; aw[q] += hk * w4.w;
                }
            }
        }
    }
    if (active) {
#pragma unroll
        for (int q = 0; q < 4; q++) {
            int u = lane + 32 * q;
            float c1 = sigm_fast(ay[q]) * c0[q] + sigm_fast(ax[q]) * tanh_fast(az[q]);
            float h1 = sigm_fast(aw[q]) * tanh_fast(c1);
            float h1p = __shfl_xor_sync(~0u, h1, 1);
            if ((lane & 1) == 0) {
                int k2 = u >> 1;
                int gb = k2 & ~7, w = k2 & 7;
                int pos = gb + ((w & 3) << 1) + (w >> 2);
                g_hclsP[(dir * 625 + cls) * 64 + pos] = packbf(h1, h1p);
            }
            g_ccls[(dir * 625 + cls) * 128 + u] = c1;
        }
    }
}

// ---------------- CSR build ----------------
__global__ void k_deg(const int* __restrict__ t_heads, const int* __restrict__ t_tails) {
    int e = blockIdx.x * blockDim.x + threadIdx.x;
    if (e < E_) {
        atomicAdd(&g_deg[t_tails[e]], 1);
        atomicAdd(&g_deg[t_heads[e]], 1);
    }
}

__global__ void k_scan() {
    __shared__ int part[1024];
    int tid = threadIdx.x;
    int s = tid * 49, e = min(s + 49, N_);
    int sum = 0;
    for (int i = s; i < e; i++) sum += g_deg[i];
    part[tid] = sum;
    __syncthreads();
    for (int off = 1; off < 1024; off <<= 1) {
        int v = (tid >= off) ? part[tid - off] : 0;
        __syncthreads();
        part[tid] += v;
        __syncthreads();
    }
    int run = tid ? part[tid - 1] : 0;
    for (int i = s; i < e; i++) {
        g_rowptr[i] = run;
        g_cursor[i] = run;
        run += g_deg[i];
    }
    if (tid == 1023) g_rowptr[N_] = part[1023];
}

__global__ void k_fill(const int* __restrict__ rels, const int* __restrict__ t_heads,
                       const int* __restrict__ t_tails) {
    int e = blockIdx.x * blockDim.x + threadIdx.x;
    if (e >= E_) return;
    int rel = rels[e], hd = t_heads[e], tl = t_tails[e];
    int wb = __float_as_int(g_attn[hd * OPS_ + rel]);
    int p1 = atomicAdd(&g_cursor[tl], 1);
    g_csr2[p1] = make_int2((hd << 5) | rel, wb);
    int p2 = atomicAdd(&g_cursor[hd], 1);
    g_csr2[p2] = make_int2((tl << 5) | (rel + 12), wb);
}

// ---------------- entity BiLSTM steps 2..7: bf16, resident Whh, dbl-buf h -------
// words: hp0 64*74=4736 | hp1 4736 | brs 64*520=33280 | sdeg 512 | scls 64
#define HP0 0
#define HP1 4736
#define BRS 9472
#define SDG 42752
#define SCL 43264
#define ESMEM (43328 * 4)

__global__ void __launch_bounds__(512, 1) k_entity2(const int* __restrict__ degrees) {
    extern __shared__ unsigned smu[];
    unsigned* brs = smu + BRS;
    int* sdeg = (int*)(smu + SDG);
    int* scls = (int*)(smu + SCL);

    const int tid = threadIdx.x, lane = tid & 31, wid = tid >> 5;
    const int dir = blockIdx.y;
    const int n0 = blockIdx.x * 64;
    const unsigned* Wb = g_Wb + dir * 32768;
    const float* xg = g_xgI + dir * 25 * 512;

    {
        int row = tid >> 3, t = tid & 7, n = n0 + row;
        sdeg[tid] = (n < N_) ? degrees[n * 8 + (dir ? 7 - t : t)] : 0;
    }
    __syncthreads();
    if (tid < 64) scls[tid] = sdeg[tid * 8] * 25 + sdeg[tid * 8 + 1];
    __syncthreads();

    // init h (bf16x2, permuted) into buffer 0
    for (int i = tid; i < 64 * 64; i += 512) {
        int row = i >> 6, p = i & 63;
        smu[HP0 + row * 74 + p] = g_hclsP[(dir * 625 + scls[row]) * 64 + p];
    }
    // preload full Whh (packed bf16x2)
#pragma unroll
    for (int q = 0; q < 16; q++) {
        int idx = tid + q * 512;
        int r = idx >> 7, c4 = idx & 127;
        *(uint4*)&brs[r * 520 + c4 * 4] = *(const uint4*)&Wb[r * 512 + c4 * 4];
    }

    const int par = lane & 1;
    float cst[16];
#pragma unroll
    for (int mf = 0; mf < 4; mf++)
#pragma unroll
        for (int nf = 0; nf < 4; nf++) {
            int row = mf * 16 + (lane >> 2) + 8 * par;
            int u = wid * 8 + nf * 2 + ((lane & 3) >> 1);
            cst[mf * 4 + nf] = g_ccls[(dir * 625 + scls[row]) * 128 + u];
        }
    __syncthreads();

    for (int step = 2; step < 8; step++) {
        const unsigned* hpR = smu + ((step & 1) ? HP1 : HP0);
        unsigned short* hpW = (unsigned short*)(smu + ((step & 1) ? HP0 : HP1));

        float acc[4][4][4];
#pragma unroll
        for (int mf = 0; mf < 4; mf++)
#pragma unroll
            for (int nf = 0; nf < 4; nf++)
#pragma unroll
                for (int q = 0; q < 4; q++) acc[mf][nf][q] = 0.f;

#pragma unroll
        for (int sub = 0; sub < 8; sub++) {
            int kro = sub * 8;
            unsigned b0[4], b1[4];
#pragma unroll
            for (int nf = 0; nf < 4; nf++) {
                int col = wid * 32 + nf * 8 + (lane >> 2);
                b0[nf] = brs[(kro + (lane & 3)) * 520 + col];
                b1[nf] = brs[(kro + 4 + (lane & 3)) * 520 + col];
            }
#pragma unroll
            for (int mf = 0; mf < 4; mf++) {
                int ab = (mf * 16 + (lane >> 2)) * 74 + kro + 2 * (lane & 3);
                uint2 v0 = *(const uint2*)&hpR[ab];
                uint2 v1 = *(const uint2*)&hpR[ab + 8 * 74];
#pragma unroll
                for (int nf = 0; nf < 4; nf++)
                    mma16(acc[mf][nf], v0.x, v1.x, v0.y, v1.y, b0[nf], b1[nf]);
            }
        }
        // no barrier here: epilogue writes the OTHER h buffer

#pragma unroll
        for (int mf = 0; mf < 4; mf++)
#pragma unroll
            for (int nf = 0; nf < 4; nf++) {
                float* a = acc[mf][nf];
                float x0 = __shfl_xor_sync(~0u, par ? a[0] : a[2], 1);
                float x1 = __shfl_xor_sync(~0u, par ? a[1] : a[3], 1);
                int row = mf * 16 + (lane >> 2) + 8 * par;
                int lo = nf * 2 + ((lane & 3) >> 1);
                int u = wid * 8 + lo;
                int d = sdeg[row * 8 + step];
                float4 xv = *(const float4*)&xg[d * 512 + u * 4];
                float iv, fv, gv, ov;
                if (par) { iv = x0; fv = x1; gv = a[2]; ov = a[3]; }
                else     { iv = a[0]; fv = a[1]; gv = x0; ov = x1; }
                iv += xv.x; fv += xv.y; gv += xv.z; ov += xv.w;
                float c = cst[mf * 4 + nf];
                c = sigm_fast(fv) * c + sigm_fast(iv) * tanh_fast(gv);
                cst[mf * 4 + nf] = c;
                float h = sigm_fast(ov) * tanh_fast(c);
                if (step < 7) {
                    int k2 = wid * 4 + nf;
                    int gb = k2 & ~7, w = k2 & 7;
                    int pos = gb + ((w & 3) << 1) + (w >> 2);
                    int eps = (lane & 3) >> 1;   // low/high half of the bf16x2 word
                    hpW[(row * 74 + pos) * 2 + eps] = bf16of(h);
                } else {
                    int n = n0 + row;
                    if (n < N_) g_eh[n * 256 + dir * 128 + u] = h;
                }
            }
        __syncthreads();
    }
}

// ---------------- entity attention ----------------
__global__ void k_eattn(const float* __restrict__ e_lin_W, const float* __restrict__ e_lin_b) {
    __shared__ float sw[24 * 256];
    __shared__ float sb[24];
    int tid = threadIdx.x;
    for (int i = tid; i < 24 * 256; i += 256) sw[i] = e_lin_W[i];
    if (tid < 24) sb[tid] = e_lin_b[tid];
    __syncthreads();
    int lane = tid & 31;
    for (int n = blockIdx.x * 8 + (tid >> 5); n < N_; n += gridDim.x * 8) {
        float h[8];
        const float* hpx = g_eh + n * 256;
#pragma unroll
        for (int j = 0; j < 8; j++) h[j] = hpx[lane + 32 * j];
        float mine = -1e30f;
#pragma unroll
        for (int op = 0; op < 24; op++) {
            const float* wp = sw + op * 256 + lane;
            float s = 0.f;
#pragma unroll
            for (int j = 0; j < 8; j++) s += h[j] * wp[32 * j];
            for (int o = 16; o; o >>= 1) s += __shfl_xor_sync(~0u, s, o);
            if (lane == op) mine = s + sb[op];
        }
        float mx = mine;
        for (int o = 16; o; o >>= 1) mx = fmaxf(mx, __shfl_xor_sync(~0u, mx, o));
        float e = (lane < 24) ? expf(mine - mx) : 0.f;
        float sum = e;
        for (int o = 16; o; o >>= 1) sum += __shfl_xor_sync(~0u, sum, o);
        if (lane < 24) g_attn[n * 24 + lane] = e / sum;
    }
}

// ---------------- query path ----------------
__global__ void k_qtr(const float* __restrict__ qWih, const float* __restrict__ qWhh) {
    __shared__ float t[32][33];
    int m = blockIdx.z;
    const float* src = (m < 6) ? qWih + m * 512 * 128 : qWhh + (m - 6) * 512 * 128;
    float* dst = (m < 6) ? g_qWihT + m * 128 * 512 : g_qWhhT + (m - 6) * 128 * 512;
    int r0 = blockIdx.x * 32, k0 = blockIdx.y * 32;
    int tx = threadIdx.x, ty = threadIdx.y;
#pragma unroll
    for (int j = 0; j < 32; j += 8) t[ty + j][tx] = src[(r0 + ty + j) * 128 + k0 + tx];
    __syncthreads();
#pragma unroll
    for (int j = 0; j < 32; j += 8) dst[(k0 + ty + j) * 512 + r0 + tx] = t[tx][ty + j];
}

__global__ void __launch_bounds__(512) k_qlstm2(const int* __restrict__ queries,
                                                const float* __restrict__ q_emb,
                                                const float* __restrict__ q_bih,
                                                const float* __restrict__ q_bhh) {
    __shared__ float xs[8][128];
    __shared__ float hs[8][128];
    __shared__ float gsm[8][512];
    int tid = threadIdx.x;
    int rd = blockIdx.x >> 2, bg = blockIdx.x & 3, b0 = bg * 8;
    for (int i = tid; i < 1024; i += 512) {
        int b = i >> 7, k = i & 127;
        xs[b][k] = q_emb[queries[b0 + b] * 128 + k];
        hs[b][k] = 0.f;
    }
    __syncthreads();
    const float* WihT = g_qWihT + rd * 65536;
    const float* WhhT = g_qWhhT + rd * 65536;
    float bias = q_bih[rd * 512 + tid] + q_bhh[rd * 512 + tid];
    float xw[8];
#pragma unroll
    for (int b = 0; b < 8; b++) xw[b] = bias;
    for (int k = 0; k < 128; k++) {
        float w = WihT[k * 512 + tid];
#pragma unroll
        for (int b = 0; b < 8; b++) xw[b] += xs[b][k] * w;
    }
    float c2[2] = {0.f, 0.f};
    int j = tid & 127, bb0 = (tid >> 7) * 2;
    for (int t = 0; t < 3; t++) {
        float acc[8];
#pragma unroll
        for (int b = 0; b < 8; b++) acc[b] = xw[b];
        for (int k = 0; k < 128; k++) {
            float w = WhhT[k * 512 + tid];
#pragma unroll
            for (int b = 0; b < 8; b++) acc[b] += hs[b][k] * w;
        }
#pragma unroll
        for (int b = 0; b < 8; b++) gsm[b][tid] = acc[b];
        __syncthreads();
#pragma unroll
        for (int e = 0; e < 2; e++) {
            int b = bb0 + e;
            float iv = gsm[b][j], fv = gsm[b][128 + j];
            float gv = gsm[b][256 + j], ov = gsm[b][384 + j];
            c2[e] = sigm(fv) * c2[e] + sigm(iv) * tanhf(gv);
            float h = sigm(ov) * tanhf(c2[e]);
            hs[b][j] = h;
            g_qys[((rd * 3 + t) * B_ + b0 + b) * H_ + j] = h;
        }
        __syncthreads();
    }
}

__global__ void k_qattn(const float* __restrict__ q_lin_W, const float* __restrict__ q_lin_b) {
    int w = (blockIdx.x * blockDim.x + threadIdx.x) >> 5;
    int lane = threadIdx.x & 31;
    if (w >= R_ * T_ * B_) return;
    int b = w & 31, t = (w >> 5) % 3, r = w / 96;
    const float* ysf = g_qys + (((r * 2 + 0) * 3 + t) * B_ + b) * H_;
    const float* ysb = g_qys + (((r * 2 + 1) * 3 + (2 - t)) * B_ + b) * H_;
    float s = -1e30f;
    if (lane <= OPS_) {
        s = q_lin_b[lane];
        const float* wv = q_lin_W + lane * 256;
        for (int k = 0; k < 128; k++) s += ysf[k] * wv[k];
        for (int k = 0; k < 128; k++) s += ysb[k] * wv[128 + k];
    }
    float mx = s;
    for (int o = 16; o; o >>= 1) mx = fmaxf(mx, __shfl_xor_sync(~0u, mx, o));
    float e = (lane <= OPS_) ? expf(s - mx) : 0.f;
    float sum = e;
    for (int o = 16; o; o >>= 1) sum += __shfl_xor_sync(~0u, sum, o);
    if (lane <= OPS_) g_qaT[((r * 3 + t) * (OPS_ + 1) + lane) * B_ + b] = e / sum;
}

// ---------------- t=0 propagation ----------------
__global__ void k_prop0(float* __restrict__ memout, const int* __restrict__ heads, int rt) {
    __shared__ float qs[25 * 32];
    int tid = threadIdx.x, lane = tid & 31, wrp = tid >> 5;
    const float* qsrc = g_qaT + rt * 25 * 32;
    for (int i = tid; i < 800; i += 1024) qs[i] = qsrc[i];
    __syncthreads();
    int b = wrp;
    int hb = heads[b];
    float q24 = qs[24 * 32 + b];
    int p0 = g_rowptr[hb], p1 = g_rowptr[hb + 1];
    float lsum = 0.f;
    for (int p = p0 + lane; p < p1; p += 32) {
        int2 e = g_csr2[p];
        int s = e.x >> 5, idx = e.x & 31;
        int qi = (idx < 12) ? (idx + 12) : (idx - 12);
        float v = qs[qi * 32 + b] * __int_as_float(e.y);
        atomicAdd(&memout[s * 32 + b], v);
        lsum += v;
    }
    for (int o = 16; o; o >>= 1) lsum += __shfl_xor_sync(~0u, lsum, o);
    if (lane == 0) {
        atomicAdd(&memout[hb * 32 + b], q24);
        atomicAdd(&g_sums[rt * 32 + b], lsum + q24);
    }
}

// ---------------- t>0 propagation ----------------
__global__ void __launch_bounds__(256) k_prop(const float* __restrict__ memin,
                                              float* __restrict__ memout,
                                              int rt, int rtprev) {
    __shared__ float qs[25 * 32];
    __shared__ float red[8][32];
    int tid = threadIdx.x, lane = tid & 31, wrp = tid >> 5;
    const float* qsrc = g_qaT + rt * 25 * 32;
    for (int i = tid; i < 800; i += 256) qs[i] = qsrc[i];
    __syncthreads();

    float sp = 1.f / fmaxf(1e-20f, g_sums[rtprev * 32 + lane]);
    float q24 = qs[24 * 32 + lane];

    float lsum = 0.f;
    int nwarps = (gridDim.x * blockDim.x) >> 5;
    for (int n = (blockIdx.x * blockDim.x + tid) >> 5; n < N_; n += nwarps) {
        int p0 = g_rowptr[n], p1 = g_rowptr[n + 1];
        float acc = memin[n * 32 + lane] * q24;
        int nfull = (p1 - p0) & ~3;
        int pend = p0 + nfull;
        int p = p0;
        int2 ee[4];
        if (p < pend) {
#pragma unroll
            for (int j = 0; j < 4; j++) ee[j] = g_csr2[p + j];
        }
        while (p < pend) {
            float mm[4];
#pragma unroll
            for (int j = 0; j < 4; j++) mm[j] = memin[(ee[j].x >> 5) * 32 + lane];
            int2 en[4];
            if (p + 4 < pend) {
#pragma unroll
                for (int j = 0; j < 4; j++) en[j] = g_csr2[p + 4 + j];
            }
#pragma unroll
            for (int j = 0; j < 4; j++)
                acc += qs[(ee[j].x & 31) * 32 + lane] * __int_as_float(ee[j].y) * mm[j];
#pragma unroll
            for (int j = 0; j < 4; j++) ee[j] = en[j];
            p += 4;
        }
        for (; p < p1; p++) {
            int2 e = g_csr2[p];
            acc += qs[(e.x & 31) * 32 + lane] * __int_as_float(e.y) *
                   memin[(e.x >> 5) * 32 + lane];
        }
        acc *= sp;
        memout[n * 32 + lane] = acc;
        lsum += acc;
    }
    red[wrp][lane] = lsum;
    __syncthreads();
    if (wrp == 0) {
        float s = 0.f;
#pragma unroll
        for (int q = 0; q < 8; q++) s += red[q][lane];
        atomicAdd(&g_sums[rt * 32 + lane], s);
    }
}

// ---------------- transposed accumulate ----------------
__global__ void k_accum(const float* __restrict__ memlast, float* __restrict__ out, int rtl) {
    __shared__ float t[32][33];
    int n0 = blockIdx.x * 32;
    int tx = threadIdx.x & 31, ty = threadIdx.x >> 5;
#pragma unroll
    for (int j = 0; j < 32; j += 8) {
        int n = n0 + ty + j;
        if (n < N_) t[ty + j][tx] = memlast[n * 32 + tx];
    }
    __syncthreads();
    int n = n0 + tx;
    if (n < N_) {
#pragma unroll
        for (int j = 0; j < 32; j += 8) {
            int b = ty + j;
            float inv = 1.f / fmaxf(1e-20f, g_sums[rtl * 32 + b]);
            out[b * N_ + n] += t[tx][b] * inv;
        }
    }
}

// ---------------- host ----------------
extern "C" void kernel_launch(void* const* d_in, const int* in_sizes, int n_in,
                              void* d_out, int out_size) {
    const int* queries   = (const int*)d_in[0];
    const int* heads     = (const int*)d_in[1];
    const int* rels      = (const int*)d_in[2];
    const int* t_heads   = (const int*)d_in[3];
    const int* t_tails   = (const int*)d_in[4];
    const int* degrees   = (const int*)d_in[5];
    const float* q_emb   = (const float*)d_in[6];
    const float* ent_emb = (const float*)d_in[7];
    const float* q_Wih   = (const float*)d_in[8];
    const float* q_Whh   = (const float*)d_in[9];
    const float* q_bih   = (const float*)d_in[10];
    const float* q_bhh   = (const float*)d_in[11];
    const float* e_Wih   = (const float*)d_in[12];
    const float* e_Whh   = (const float*)d_in[13];
    const float* e_bih   = (const float*)d_in[14];
    const float* e_bhh   = (const float*)d_in[15];
    const float* q_lin_W = (const float*)d_in[16];
    const float* q_lin_b = (const float*)d_in[17];
    const float* e_lin_W = (const float*)d_in[18];
    const float* e_lin_b = (const float*)d_in[19];
    float* out = (float*)d_out;

    void *p_sums, *p_deg, *p_memA, *p_memB;
    cudaGetSymbolAddress(&p_sums, g_sums);
    cudaGetSymbolAddress(&p_deg, g_deg);
    cudaGetSymbolAddress(&p_memA, g_memA);
    cudaGetSymbolAddress(&p_memB, g_memB);
    float* memA = (float*)p_memA;
    float* memB = (float*)p_memB;

    // launches 1..5, then k_entity2 at #6 (ncu -s 5 -c 1 capture slot)
    cudaMemsetAsync(d_out, 0, (size_t)N_ * B_ * sizeof(float));
    k_xg<<<dim3(25, 2), 512>>>(ent_emb, e_Wih, e_bih, e_bhh);
    k_whhT<<<dim3(128, 2), 512>>>(e_Whh);
    k_wpack<<<128, 512>>>();
    k_cls<<<dim3(79, 2), 256>>>();

    cudaFuncSetAttribute(k_entity2, cudaFuncAttributeMaxDynamicSharedMemorySize, ESMEM);
    k_entity2<<<dim3((N_ + 63) / 64, 2), 512, ESMEM>>>(degrees);

    cudaMemsetAsync(p_sums, 0, R_ * T_ * B_ * sizeof(float));
    cudaMemsetAsync(p_deg, 0, N_ * sizeof(int));
    k_qtr<<<dim3(16, 4, 12), dim3(32, 8)>>>(q_Wih, q_Whh);
    k_deg<<<(E_ + 255) / 256, 256>>>(t_heads, t_tails);
    k_scan<<<1, 1024>>>();
    k_eattn<<<782, 256>>>(e_lin_W, e_lin_b);
    k_fill<<<(E_ + 255) / 256, 256>>>(rels, t_heads, t_tails);

    k_qlstm2<<<24, 512>>>(queries, q_emb, q_bih, q_bhh);
    k_qattn<<<36, 256>>>(q_lin_W, q_lin_b);

    for (int r = 0; r < R_; r++) {
        int rt0 = r * 3;
        cudaMemsetAsync(p_memB, 0, (size_t)N_ * B_ * sizeof(float));
        k_prop0<<<1, 1024>>>(memB, heads, rt0);
        k_prop<<<1480, 256>>>(memB, memA, rt0 + 1, rt0);
        k_prop<<<1480, 256>>>(memA, memB, rt0 + 2, rt0 + 1);
        k_accum<<<(N_ + 31) / 32, 256>>>(memB, out, rt0 + 2);
    }
}

// round 16
// speedup vs baseline: 1.0259x; 1.0259x over previous
#include <cuda_runtime.h>
#include <math.h>

#define R_ 3
#define T_ 3
#define N_ 50000
#define OPS_ 24
#define E_ 400000
#define B_ 32
#define MAXDEG_ 8
#define QD_ 128
#define H_ 128

// ---------------- device scratch ----------------
__device__ float g_xgI[2 * 25 * 512];
__device__ float g_Wt[2 * 128 * 512];
__device__ unsigned g_Wb[2 * 64 * 512];
__device__ unsigned g_hclsP[2 * 625 * 64];
__device__ float g_ccls[2 * 625 * 128];
__device__ float g_eh[N_ * 256];
__device__ float g_attn[N_ * OPS_];
__device__ float g_qWihT[6 * 128 * 512];
__device__ float g_qWhhT[6 * 128 * 512];
__device__ float g_qys[R_ * 2 * T_ * B_ * H_];
__device__ float g_qaT[R_ * T_ * (OPS_ + 1) * B_];
__device__ float g_memA[N_ * B_];
__device__ float g_memB[N_ * B_];
__device__ float g_sums[R_ * T_ * B_];
__device__ int g_deg[N_];
__device__ int g_rowptr[N_ + 1];
__device__ int g_cursor[N_];
__device__ int2 g_csr2[2 * E_];

__device__ __forceinline__ float sigm(float x) { return 1.f / (1.f + expf(-x)); }
__device__ __forceinline__ float tanh_fast(float x) {
    float y; asm("tanh.approx.f32 %0, %1;" : "=f"(y) : "f"(x)); return y;
}
__device__ __forceinline__ float sigm_fast(float x) { return 0.5f + 0.5f * tanh_fast(0.5f * x); }
__device__ __forceinline__ unsigned f2tf32(float x) {
    unsigned y; asm("cvt.rna.tf32.f32 %0, %1;" : "=r"(y) : "f"(x)); return y;
}
__device__ __forceinline__ unsigned packbf(float lo, float hi) {
    unsigned r; asm("cvt.rn.bf16x2.f32 %0, %1, %2;" : "=r"(r) : "f"(hi), "f"(lo)); return r;
}
__device__ __forceinline__ void mma16(float* c, unsigned a0, unsigned a1, unsigned a2,
                                      unsigned a3, unsigned b0, unsigned b1) {
    asm volatile("mma.sync.aligned.m16n8k16.row.col.f32.bf16.bf16.f32 "
                 "{%0,%1,%2,%3},{%4,%5,%6,%7},{%8,%9},{%0,%1,%2,%3};"
                 : "+f"(c[0]), "+f"(c[1]), "+f"(c[2]), "+f"(c[3])
                 : "r"(a0), "r"(a1), "r"(a2), "r"(a3), "r"(b0), "r"(b1));
}

// ---------------- precompute ----------------
__global__ void k_xg(const float* __restrict__ ent_emb, const float* __restrict__ e_Wih,
                     const float* __restrict__ e_bih, const float* __restrict__ e_bhh) {
    int d = blockIdx.x, dir = blockIdx.y, tid = threadIdx.x;
    int j = tid >> 2, g = tid & 3;
    int row = g * 128 + j;
    const float* w = e_Wih + (dir * 512 + row) * 128;
    const float* x = ent_emb + d * 128;
    float s = e_bih[dir * 512 + row] + e_bhh[dir * 512 + row];
    for (int k = 0; k < 128; k++) s += x[k] * w[k];
    g_xgI[(dir * 25 + d) * 512 + tid] = s;
}

__global__ void k_whhT(const float* __restrict__ e_Whh) {
    int k = blockIdx.x, dir = blockIdx.y, tid = threadIdx.x;
    int j = tid >> 2, g = tid & 3;
    float v = e_Whh[(dir * 512 + g * 128 + j) * 128 + k];
    g_Wt[(dir * 128 + k) * 512 + tid] = __uint_as_float(f2tf32(v));
}

// ---------------- class table (+ bf16 weight pack prologue) ----------------
__global__ void k_cls() {
    __shared__ float sw[16 * 516];
    __shared__ float sh0[8][128];
    int tid = threadIdx.x, warp = tid >> 5, lane = tid & 31;
    int cls = blockIdx.x * 8 + warp;
    int dir = blockIdx.y;
    const float* Wt = g_Wt + dir * 128 * 512;

    // pack Whh to bf16x2 for this dir (grid-stride over 64*512 entries)
    for (int i = blockIdx.x * 256 + tid; i < 64 * 512; i += 79 * 256) {
        int k2 = i >> 9, col = i & 511;
        g_Wb[dir * 32768 + i] = packbf(Wt[(2 * k2) * 512 + col],
                                       Wt[(2 * k2 + 1) * 512 + col]);
    }

    bool active = (cls < 625);
    int d0 = 0, d1 = 0;
    if (active) { d0 = cls / 25; d1 = cls - d0 * 25; }
    const float* xg0 = g_xgI + (dir * 25 + d0) * 512;
    const float* xg1 = g_xgI + (dir * 25 + d1) * 512;

    float c0[4];
    float ax[4], ay[4], az[4], aw[4];
    if (active) {
#pragma unroll
        for (int q = 0; q < 4; q++) {
            int u = lane + 32 * q;
            float4 xv = *(const float4*)&xg0[u * 4];
            c0[q] = sigm_fast(xv.x) * tanh_fast(xv.z);
            float h0 = sigm_fast(xv.w) * tanh_fast(c0[q]);
            sh0[warp][u] = __uint_as_float(f2tf32(h0));
            float4 a1 = *(const float4*)&xg1[u * 4];
            ax[q] = a1.x; ay[q] = a1.y; az[q] = a1.z; aw[q] = a1.w;
        }
    }
    for (int ch = 0; ch < 8; ch++) {
        __syncthreads();
#pragma unroll
        for (int q = 0; q < 8; q++) {
            int i = tid + q * 256;
            int r = i >> 7, c4 = i & 127;
            *(float4*)&sw[r * 516 + c4 * 4] = *(const float4*)&Wt[(ch * 16 + r) * 512 + c4 * 4];
        }
        __syncthreads();
        if (active) {
#pragma unroll
            for (int kk = 0; kk < 16; kk++) {
                float hk = sh0[warp][ch * 16 + kk];
#pragma unroll
                for (int q = 0; q < 4; q++) {
                    float4 w4 = *(const float4*)&sw[kk * 516 + (lane + 32 * q) * 4];
                    ax[q] += hk * w4.x; ay[q] += hk * w4.y;
                    az[q] += hk * w4.z; aw[q] += hk * w4.w;
                }
            }
        }
    }
    if (active) {
#pragma unroll
        for (int q = 0; q < 4; q++) {
            int u = lane + 32 * q;
            float c1 = sigm_fast(ay[q]) * c0[q] + sigm_fast(ax[q]) * tanh_fast(az[q]);
            float h1 = sigm_fast(aw[q]) * tanh_fast(c1);
            float h1p = __shfl_xor_sync(~0u, h1, 1);
            if ((lane & 1) == 0) {
                int k2 = u >> 1;
                int gb = k2 & ~7, w = k2 & 7;
                int pos = gb + ((w & 3) << 1) + (w >> 2);
                g_hclsP[(dir * 625 + cls) * 64 + pos] = packbf(h1, h1p);
            }
            g_ccls[(dir * 625 + cls) * 128 + u] = c1;
        }
    }
}

// ---------------- entity BiLSTM steps 2..7: bf16 MMA, fully resident Whh --------
// smem words: hp 64*72=4608 | brs 64*520=33280 | sdeg 512 | scls 64 -> 38464 w
#define HPW 0
#define BRS 4608
#define SDG 37888
#define SCL 38400
#define ESMEM (38464 * 4)

__global__ void __launch_bounds__(512, 1) k_entity2(const int* __restrict__ degrees) {
    extern __shared__ unsigned smu[];
    unsigned* hp = smu + HPW;
    unsigned* brs = smu + BRS;
    int* sdeg = (int*)(smu + SDG);
    int* scls = (int*)(smu + SCL);

    const int tid = threadIdx.x, lane = tid & 31, wid = tid >> 5;
    const int dir = blockIdx.y;
    const int n0 = blockIdx.x * 64;
    const unsigned* Wb = g_Wb + dir * 32768;
    const float* xg = g_xgI + dir * 25 * 512;

    {
        int row = tid >> 3, t = tid & 7, n = n0 + row;
        sdeg[tid] = (n < N_) ? degrees[n * 8 + (dir ? 7 - t : t)] : 0;
    }
    __syncthreads();
    if (tid < 64) scls[tid] = sdeg[tid * 8] * 25 + sdeg[tid * 8 + 1];
    __syncthreads();

    for (int i = tid; i < 64 * 64; i += 512) {
        int row = i >> 6, p = i & 63;
        hp[row * 72 + p] = g_hclsP[(dir * 625 + scls[row]) * 64 + p];
    }
#pragma unroll
    for (int q = 0; q < 16; q++) {
        int idx = tid + q * 512;
        int r = idx >> 7, c4 = idx & 127;
        *(uint4*)&brs[r * 520 + c4 * 4] = *(const uint4*)&Wb[r * 512 + c4 * 4];
    }

    const int par = lane & 1;
    float cst[16];
#pragma unroll
    for (int mf = 0; mf < 4; mf++)
#pragma unroll
        for (int nf = 0; nf < 4; nf++) {
            int row = mf * 16 + (lane >> 2) + 8 * par;
            int u = wid * 8 + nf * 2 + ((lane & 3) >> 1);
            cst[mf * 4 + nf] = g_ccls[(dir * 625 + scls[row]) * 128 + u];
        }
    __syncthreads();

    for (int step = 2; step < 8; step++) {
        float acc[4][4][4];
#pragma unroll
        for (int mf = 0; mf < 4; mf++)
#pragma unroll
            for (int nf = 0; nf < 4; nf++)
#pragma unroll
                for (int q = 0; q < 4; q++) acc[mf][nf][q] = 0.f;

#pragma unroll
        for (int sub = 0; sub < 8; sub++) {
            int kro = sub * 8;
            unsigned b0[4], b1[4];
#pragma unroll
            for (int nf = 0; nf < 4; nf++) {
                int col = wid * 32 + nf * 8 + (lane >> 2);
                b0[nf] = brs[(kro + (lane & 3)) * 520 + col];
                b1[nf] = brs[(kro + 4 + (lane & 3)) * 520 + col];
            }
#pragma unroll
            for (int mf = 0; mf < 4; mf++) {
                int ab = (mf * 16 + (lane >> 2)) * 72 + kro + 2 * (lane & 3);
                uint2 v0 = *(const uint2*)&hp[ab];
                uint2 v1 = *(const uint2*)&hp[ab + 8 * 72];
#pragma unroll
                for (int nf = 0; nf < 4; nf++)
                    mma16(acc[mf][nf], v0.x, v1.x, v0.y, v1.y, b0[nf], b1[nf]);
            }
        }
        __syncthreads();   // all h reads done before epilogue writes

#pragma unroll
        for (int mf = 0; mf < 4; mf++)
#pragma unroll
            for (int nf = 0; nf < 4; nf++) {
                float* a = acc[mf][nf];
                float x0 = __shfl_xor_sync(~0u, par ? a[0] : a[2], 1);
                float x1 = __shfl_xor_sync(~0u, par ? a[1] : a[3], 1);
                int row = mf * 16 + (lane >> 2) + 8 * par;
                int lo = nf * 2 + ((lane & 3) >> 1);
                int u = wid * 8 + lo;
                int d = sdeg[row * 8 + step];
                float4 xv = *(const float4*)&xg[d * 512 + u * 4];
                float iv, fv, gv, ov;
                if (par) { iv = x0; fv = x1; gv = a[2]; ov = a[3]; }
                else     { iv = a[0]; fv = a[1]; gv = x0; ov = x1; }
                iv += xv.x; fv += xv.y; gv += xv.z; ov += xv.w;
                float c = cst[mf * 4 + nf];
                c = sigm_fast(fv) * c + sigm_fast(iv) * tanh_fast(gv);
                cst[mf * 4 + nf] = c;
                float h = sigm_fast(ov) * tanh_fast(c);
                if (step < 7) {
                    float hq = __shfl_xor_sync(~0u, h, 2);
                    if ((lane & 2) == 0) {
                        int k2 = u >> 1;
                        int gb = k2 & ~7, w = k2 & 7;
                        int pos = gb + ((w & 3) << 1) + (w >> 2);
                        hp[row * 72 + pos] = packbf(h, hq);
                    }
                } else {
                    int n = n0 + row;
                    if (n < N_) g_eh[n * 256 + dir * 128 + u] = h;
                }
            }
        __syncthreads();
    }
}

// ---------------- entity attention ----------------
__global__ void k_eattn(const float* __restrict__ e_lin_W, const float* __restrict__ e_lin_b) {
    __shared__ float sw[24 * 256];
    __shared__ float sb[24];
    int tid = threadIdx.x;
    for (int i = tid; i < 24 * 256; i += 256) sw[i] = e_lin_W[i];
    if (tid < 24) sb[tid] = e_lin_b[tid];
    __syncthreads();
    int lane = tid & 31;
    for (int n = blockIdx.x * 8 + (tid >> 5); n < N_; n += gridDim.x * 8) {
        float h[8];
        const float* hpx = g_eh + n * 256;
#pragma unroll
        for (int j = 0; j < 8; j++) h[j] = hpx[lane + 32 * j];
        float mine = -1e30f;
#pragma unroll
        for (int op = 0; op < 24; op++) {
            const float* wp = sw + op * 256 + lane;
            float s = 0.f;
#pragma unroll
            for (int j = 0; j < 8; j++) s += h[j] * wp[32 * j];
            for (int o = 16; o; o >>= 1) s += __shfl_xor_sync(~0u, s, o);
            if (lane == op) mine = s + sb[op];
        }
        float mx = mine;
        for (int o = 16; o; o >>= 1) mx = fmaxf(mx, __shfl_xor_sync(~0u, mx, o));
        float e = (lane < 24) ? expf(mine - mx) : 0.f;
        float sum = e;
        for (int o = 16; o; o >>= 1) sum += __shfl_xor_sync(~0u, sum, o);
        if (lane < 24) g_attn[n * 24 + lane] = e / sum;
    }
}

// ---------------- CSR build ----------------
__global__ void k_deg(const int* __restrict__ t_heads, const int* __restrict__ t_tails) {
    int e = blockIdx.x * blockDim.x + threadIdx.x;
    if (e < E_) {
        atomicAdd(&g_deg[t_tails[e]], 1);
        atomicAdd(&g_deg[t_heads[e]], 1);
    }
}

__global__ void k_scan() {
    __shared__ int part[1024];
    int tid = threadIdx.x;
    int s = tid * 49, e = min(s + 49, N_);
    int sum = 0;
    for (int i = s; i < e; i++) sum += g_deg[i];
    part[tid] = sum;
    __syncthreads();
    for (int off = 1; off < 1024; off <<= 1) {
        int v = (tid >= off) ? part[tid - off] : 0;
        __syncthreads();
        part[tid] += v;
        __syncthreads();
    }
    int run = tid ? part[tid - 1] : 0;
    for (int i = s; i < e; i++) {
        g_rowptr[i] = run;
        g_cursor[i] = run;
        run += g_deg[i];
    }
    if (tid == 1023) g_rowptr[N_] = part[1023];
}

__global__ void k_fill(const int* __restrict__ rels, const int* __restrict__ t_heads,
                       const int* __restrict__ t_tails) {
    int e = blockIdx.x * blockDim.x + threadIdx.x;
    if (e >= E_) return;
    int rel = rels[e], hd = t_heads[e], tl = t_tails[e];
    int wb = __float_as_int(g_attn[hd * OPS_ + rel]);
    int p1 = atomicAdd(&g_cursor[tl], 1);
    g_csr2[p1] = make_int2((hd << 5) | rel, wb);
    int p2 = atomicAdd(&g_cursor[hd], 1);
    g_csr2[p2] = make_int2((tl << 5) | (rel + 12), wb);
}

// ---------------- query path ----------------
__global__ void k_qtr(const float* __restrict__ qWih, const float* __restrict__ qWhh) {
    __shared__ float t[32][33];
    int m = blockIdx.z;
    const float* src = (m < 6) ? qWih + m * 512 * 128 : qWhh + (m - 6) * 512 * 128;
    float* dst = (m < 6) ? g_qWihT + m * 128 * 512 : g_qWhhT + (m - 6) * 128 * 512;
    int r0 = blockIdx.x * 32, k0 = blockIdx.y * 32;
    int tx = threadIdx.x, ty = threadIdx.y;
#pragma unroll
    for (int j = 0; j < 32; j += 8) t[ty + j][tx] = src[(r0 + ty + j) * 128 + k0 + tx];
    __syncthreads();
#pragma unroll
    for (int j = 0; j < 32; j += 8) dst[(k0 + ty + j) * 512 + r0 + tx] = t[tx][ty + j];
}

__global__ void __launch_bounds__(512) k_qlstm2(const int* __restrict__ queries,
                                                const float* __restrict__ q_emb,
                                                const float* __restrict__ q_bih,
                                                const float* __restrict__ q_bhh) {
    __shared__ float xs[8][128];
    __shared__ float hs[8][128];
    __shared__ float gsm[8][512];
    int tid = threadIdx.x;
    int rd = blockIdx.x >> 2, bg = blockIdx.x & 3, b0 = bg * 8;
    for (int i = tid; i < 1024; i += 512) {
        int b = i >> 7, k = i & 127;
        xs[b][k] = q_emb[queries[b0 + b] * 128 + k];
        hs[b][k] = 0.f;
    }
    __syncthreads();
    const float* WihT = g_qWihT + rd * 65536;
    const float* WhhT = g_qWhhT + rd * 65536;
    float bias = q_bih[rd * 512 + tid] + q_bhh[rd * 512 + tid];
    float xw[8];
#pragma unroll
    for (int b = 0; b < 8; b++) xw[b] = bias;
    for (int k = 0; k < 128; k++) {
        float w = WihT[k * 512 + tid];
#pragma unroll
        for (int b = 0; b < 8; b++) xw[b] += xs[b][k] * w;
    }
    float c2[2] = {0.f, 0.f};
    int j = tid & 127, bb0 = (tid >> 7) * 2;
    for (int t = 0; t < 3; t++) {
        float acc[8];
#pragma unroll
        for (int b = 0; b < 8; b++) acc[b] = xw[b];
        for (int k = 0; k < 128; k++) {
            float w = WhhT[k * 512 + tid];
#pragma unroll
            for (int b = 0; b < 8; b++) acc[b] += hs[b][k] * w;
        }
#pragma unroll
        for (int b = 0; b < 8; b++) gsm[b][tid] = acc[b];
        __syncthreads();
#pragma unroll
        for (int e = 0; e < 2; e++) {
            int b = bb0 + e;
            float iv = gsm[b][j], fv = gsm[b][128 + j];
            float gv = gsm[b][256 + j], ov = gsm[b][384 + j];
            c2[e] = sigm(fv) * c2[e] + sigm(iv) * tanhf(gv);
            float h = sigm(ov) * tanhf(c2[e]);
            hs[b][j] = h;
            g_qys[((rd * 3 + t) * B_ + b0 + b) * H_ + j] = h;
        }
        __syncthreads();
    }
}

__global__ void k_qattn(const float* __restrict__ q_lin_W, const float* __restrict__ q_lin_b) {
    int w = (blockIdx.x * blockDim.x + threadIdx.x) >> 5;
    int lane = threadIdx.x & 31;
    if (w >= R_ * T_ * B_) return;
    int b = w & 31, t = (w >> 5) % 3, r = w / 96;
    const float* ysf = g_qys + (((r * 2 + 0) * 3 + t) * B_ + b) * H_;
    const float* ysb = g_qys + (((r * 2 + 1) * 3 + (2 - t)) * B_ + b) * H_;
    float s = -1e30f;
    if (lane <= OPS_) {
        s = q_lin_b[lane];
        const float* wv = q_lin_W + lane * 256;
        for (int k = 0; k < 128; k++) s += ysf[k] * wv[k];
        for (int k = 0; k < 128; k++) s += ysb[k] * wv[128 + k];
    }
    float mx = s;
    for (int o = 16; o; o >>= 1) mx = fmaxf(mx, __shfl_xor_sync(~0u, mx, o));
    float e = (lane <= OPS_) ? expf(s - mx) : 0.f;
    float sum = e;
    for (int o = 16; o; o >>= 1) sum += __shfl_xor_sync(~0u, sum, o);
    if (lane <= OPS_) g_qaT[((r * 3 + t) * (OPS_ + 1) + lane) * B_ + b] = e / sum;
}

// ---------------- t=0 propagation ----------------
__global__ void k_prop0(float* __restrict__ memout, const int* __restrict__ heads, int rt) {
    __shared__ float qs[25 * 32];
    int tid = threadIdx.x, lane = tid & 31, wrp = tid >> 5;
    const float* qsrc = g_qaT + rt * 25 * 32;
    for (int i = tid; i < 800; i += 1024) qs[i] = qsrc[i];
    __syncthreads();
    int b = wrp;
    int hb = heads[b];
    float q24 = qs[24 * 32 + b];
    int p0 = g_rowptr[hb], p1 = g_rowptr[hb + 1];
    float lsum = 0.f;
    for (int p = p0 + lane; p < p1; p += 32) {
        int2 e = g_csr2[p];
        int s = e.x >> 5, idx = e.x & 31;
        int qi = (idx < 12) ? (idx + 12) : (idx - 12);
        float v = qs[qi * 32 + b] * __int_as_float(e.y);
        atomicAdd(&memout[s * 32 + b], v);
        lsum += v;
    }
    for (int o = 16; o; o >>= 1) lsum += __shfl_xor_sync(~0u, lsum, o);
    if (lane == 0) {
        atomicAdd(&memout[hb * 32 + b], q24);
        atomicAdd(&g_sums[rt * 32 + b], lsum + q24);
    }
}

// ---------------- t>0 propagation ----------------
__global__ void __launch_bounds__(256) k_prop(const float* __restrict__ memin,
                                              float* __restrict__ memout,
                                              int rt, int rtprev) {
    __shared__ float qs[25 * 32];
    __shared__ float red[8][32];
    int tid = threadIdx.x, lane = tid & 31, wrp = tid >> 5;
    const float* qsrc = g_qaT + rt * 25 * 32;
    for (int i = tid; i < 800; i += 256) qs[i] = qsrc[i];
    __syncthreads();

    float sp = 1.f / fmaxf(1e-20f, g_sums[rtprev * 32 + lane]);
    float q24 = qs[24 * 32 + lane];

    float lsum = 0.f;
    int nwarps = (gridDim.x * blockDim.x) >> 5;
    for (int n = (blockIdx.x * blockDim.x + tid) >> 5; n < N_; n += nwarps) {
        int p0 = g_rowptr[n], p1 = g_rowptr[n + 1];
        float acc = memin[n * 32 + lane] * q24;
        int nfull = (p1 - p0) & ~3;
        int pend = p0 + nfull;
        int p = p0;
        int2 ee[4];
        if (p < pend) {
#pragma unroll
            for (int j = 0; j < 4; j++) ee[j] = g_csr2[p + j];
        }
        while (p < pend) {
            float mm[4];
#pragma unroll
            for (int j = 0; j < 4; j++) mm[j] = memin[(ee[j].x >> 5) * 32 + lane];
            int2 en[4];
            if (p + 4 < pend) {
#pragma unroll
                for (int j = 0; j < 4; j++) en[j] = g_csr2[p + 4 + j];
            }
#pragma unroll
            for (int j = 0; j < 4; j++)
                acc += qs[(ee[j].x & 31) * 32 + lane] * __int_as_float(ee[j].y) * mm[j];
#pragma unroll
            for (int j = 0; j < 4; j++) ee[j] = en[j];
            p += 4;
        }
        for (; p < p1; p++) {
            int2 e = g_csr2[p];
            acc += qs[(e.x & 31) * 32 + lane] * __int_as_float(e.y) *
                   memin[(e.x >> 5) * 32 + lane];
        }
        acc *= sp;
        memout[n * 32 + lane] = acc;
        lsum += acc;
    }
    red[wrp][lane] = lsum;
    __syncthreads();
    if (wrp == 0) {
        float s = 0.f;
#pragma unroll
        for (int q = 0; q < 8; q++) s += red[q][lane];
        atomicAdd(&g_sums[rt * 32 + lane], s);
    }
}

// ---------------- transposed accumulate ----------------
__global__ void k_accum(const float* __restrict__ memlast, float* __restrict__ out, int rtl) {
    __shared__ float t[32][33];
    int n0 = blockIdx.x * 32;
    int tx = threadIdx.x & 31, ty = threadIdx.x >> 5;
#pragma unroll
    for (int j = 0; j < 32; j += 8) {
        int n = n0 + ty + j;
        if (n < N_) t[ty + j][tx] = memlast[n * 32 + tx];
    }
    __syncthreads();
    int n = n0 + tx;
    if (n < N_) {
#pragma unroll
        for (int j = 0; j < 32; j += 8) {
            int b = ty + j;
            float inv = 1.f / fmaxf(1e-20f, g_sums[rtl * 32 + b]);
            out[b * N_ + n] += t[tx][b] * inv;
        }
    }
}

// ---------------- host ----------------
extern "C" void kernel_launch(void* const* d_in, const int* in_sizes, int n_in,
                              void* d_out, int out_size) {
    const int* queries   = (const int*)d_in[0];
    const int* heads     = (const int*)d_in[1];
    const int* rels      = (const int*)d_in[2];
    const int* t_heads   = (const int*)d_in[3];
    const int* t_tails   = (const int*)d_in[4];
    const int* degrees   = (const int*)d_in[5];
    const float* q_emb   = (const float*)d_in[6];
    const float* ent_emb = (const float*)d_in[7];
    const float* q_Wih   = (const float*)d_in[8];
    const float* q_Whh   = (const float*)d_in[9];
    const float* q_bih   = (const float*)d_in[10];
    const float* q_bhh   = (const float*)d_in[11];
    const float* e_Wih   = (const float*)d_in[12];
    const float* e_Whh   = (const float*)d_in[13];
    const float* e_bih   = (const float*)d_in[14];
    const float* e_bhh   = (const float*)d_in[15];
    const float* q_lin_W = (const float*)d_in[16];
    const float* q_lin_b = (const float*)d_in[17];
    const float* e_lin_W = (const float*)d_in[18];
    const float* e_lin_b = (const float*)d_in[19];
    float* out = (float*)d_out;

    void *p_sums, *p_deg, *p_memA, *p_memB;
    cudaGetSymbolAddress(&p_sums, g_sums);
    cudaGetSymbolAddress(&p_deg, g_deg);
    cudaGetSymbolAddress(&p_memA, g_memA);
    cudaGetSymbolAddress(&p_memB, g_memB);
    float* memA = (float*)p_memA;
    float* memB = (float*)p_memB;

    cudaMemsetAsync(d_out, 0, (size_t)N_ * B_ * sizeof(float));
    cudaMemsetAsync(p_sums, 0, R_ * T_ * B_ * sizeof(float));
    cudaMemsetAsync(p_deg, 0, N_ * sizeof(int));

    // kernels 1..3, then k_entity2 as the 4th kernel launch (ncu capture slot)
    k_xg<<<dim3(25, 2), 512>>>(ent_emb, e_Wih, e_bih, e_bhh);
    k_whhT<<<dim3(128, 2), 512>>>(e_Whh);
    k_cls<<<dim3(79, 2), 256>>>();

    cudaFuncSetAttribute(k_entity2, cudaFuncAttributeMaxDynamicSharedMemorySize, ESMEM);
    k_entity2<<<dim3((N_ + 63) / 64, 2), 512, ESMEM>>>(degrees);

    k_qtr<<<dim3(16, 4, 12), dim3(32, 8)>>>(q_Wih, q_Whh);
    k_deg<<<(E_ + 255) / 256, 256>>>(t_heads, t_tails);
    k_scan<<<1, 1024>>>();
    k_eattn<<<782, 256>>>(e_lin_W, e_lin_b);
    k_fill<<<(E_ + 255) / 256, 256>>>(rels, t_heads, t_tails);

    k_qlstm2<<<24, 512>>>(queries, q_emb, q_bih, q_bhh);
    k_qattn<<<36, 256>>>(q_lin_W, q_lin_b);

    for (int r = 0; r < R_; r++) {
        int rt0 = r * 3;
        cudaMemsetAsync(p_memB, 0, (size_t)N_ * B_ * sizeof(float));
        k_prop0<<<1, 1024>>>(memB, heads, rt0);
        k_prop<<<1480, 256>>>(memB, memA, rt0 + 1, rt0);
        k_prop<<<1480, 256>>>(memA, memB, rt0 + 2, rt0 + 1);
        k_accum<<<(N_ + 31) / 32, 256>>>(memB, out, rt0 + 2);
    }
}

// round 17
// speedup vs baseline: 1.1092x; 1.0812x over previous
#include <cuda_runtime.h>
#include <math.h>

#define R_ 3
#define T_ 3
#define N_ 50000
#define OPS_ 24
#define E_ 400000
#define B_ 32
#define MAXDEG_ 8
#define QD_ 128
#define H_ 128

// ---------------- device scratch ----------------
__device__ float g_xgI[2 * 25 * 512];
__device__ float g_Wt[2 * 128 * 512];
__device__ unsigned g_Wb[2 * 64 * 512];
__device__ unsigned g_hclsN[2 * 625 * 64];   // class h after 2 steps, bf16x2, natural k2 order
__device__ float g_ccls[2 * 625 * 128];
__device__ float g_eh[N_ * 256];
__device__ float g_attn[N_ * OPS_];
__device__ float g_qWihT[6 * 128 * 512];
__device__ float g_qWhhT[6 * 128 * 512];
__device__ float g_qys[R_ * 2 * T_ * B_ * H_];
__device__ float g_qaT[R_ * T_ * (OPS_ + 1) * B_];
__device__ float g_memA[N_ * B_];
__device__ float g_memB[N_ * B_];
__device__ float g_sums[R_ * T_ * B_];
__device__ int g_deg[N_];
__device__ int g_rowptr[N_ + 1];
__device__ int g_cursor[N_];
__device__ int2 g_csr2[2 * E_];

__device__ __forceinline__ float sigm(float x) { return 1.f / (1.f + expf(-x)); }
__device__ __forceinline__ float tanh_fast(float x) {
    float y; asm("tanh.approx.f32 %0, %1;" : "=f"(y) : "f"(x)); return y;
}
__device__ __forceinline__ float sigm_fast(float x) { return 0.5f + 0.5f * tanh_fast(0.5f * x); }
__device__ __forceinline__ unsigned f2tf32(float x) {
    unsigned y; asm("cvt.rna.tf32.f32 %0, %1;" : "=r"(y) : "f"(x)); return y;
}
__device__ __forceinline__ unsigned packbf(float lo, float hi) {
    unsigned r; asm("cvt.rn.bf16x2.f32 %0, %1, %2;" : "=r"(r) : "f"(hi), "f"(lo)); return r;
}
__device__ __forceinline__ void mma16(float* c, unsigned a0, unsigned a1, unsigned a2,
                                      unsigned a3, unsigned b0, unsigned b1) {
    asm volatile("mma.sync.aligned.m16n8k16.row.col.f32.bf16.bf16.f32 "
                 "{%0,%1,%2,%3},{%4,%5,%6,%7},{%8,%9},{%0,%1,%2,%3};"
                 : "+f"(c[0]), "+f"(c[1]), "+f"(c[2]), "+f"(c[3])
                 : "r"(a0), "r"(a1), "r"(a2), "r"(a3), "r"(b0), "r"(b1));
}
__device__ __forceinline__ void ldsm4(unsigned& a0, unsigned& a1, unsigned& a2, unsigned& a3,
                                      unsigned saddr) {
    asm volatile("ldmatrix.sync.aligned.m8n8.x4.shared.b16 {%0,%1,%2,%3}, [%4];"
                 : "=r"(a0), "=r"(a1), "=r"(a2), "=r"(a3) : "r"(saddr));
}

// ---------------- precompute ----------------
__global__ void k_xg(const float* __restrict__ ent_emb, const float* __restrict__ e_Wih,
                     const float* __restrict__ e_bih, const float* __restrict__ e_bhh) {
    int d = blockIdx.x, dir = blockIdx.y, tid = threadIdx.x;
    int j = tid >> 2, g = tid & 3;
    int row = g * 128 + j;
    const float* w = e_Wih + (dir * 512 + row) * 128;
    const float* x = ent_emb + d * 128;
    float s = e_bih[dir * 512 + row] + e_bhh[dir * 512 + row];
    for (int k = 0; k < 128; k++) s += x[k] * w[k];
    g_xgI[(dir * 25 + d) * 512 + tid] = s;
}

__global__ void k_whhT(const float* __restrict__ e_Whh) {
    int k = blockIdx.x, dir = blockIdx.y, tid = threadIdx.x;
    int j = tid >> 2, g = tid & 3;
    float v = e_Whh[(dir * 512 + g * 128 + j) * 128 + k];
    g_Wt[(dir * 128 + k) * 512 + tid] = __uint_as_float(f2tf32(v));
}

// ---------------- class table (+ bf16 weight pack prologue) ----------------
__global__ void k_cls() {
    __shared__ float sw[16 * 516];
    __shared__ float sh0[8][128];
    int tid = threadIdx.x, warp = tid >> 5, lane = tid & 31;
    int cls = blockIdx.x * 8 + warp;
    int dir = blockIdx.y;
    const float* Wt = g_Wt + dir * 128 * 512;

    for (int i = blockIdx.x * 256 + tid; i < 64 * 512; i += 79 * 256) {
        int k2 = i >> 9, col = i & 511;
        g_Wb[dir * 32768 + i] = packbf(Wt[(2 * k2) * 512 + col],
                                       Wt[(2 * k2 + 1) * 512 + col]);
    }

    bool active = (cls < 625);
    int d0 = 0, d1 = 0;
    if (active) { d0 = cls / 25; d1 = cls - d0 * 25; }
    const float* xg0 = g_xgI + (dir * 25 + d0) * 512;
    const float* xg1 = g_xgI + (dir * 25 + d1) * 512;

    float c0[4];
    float ax[4], ay[4], az[4], aw[4];
    if (active) {
#pragma unroll
        for (int q = 0; q < 4; q++) {
            int u = lane + 32 * q;
            float4 xv = *(const float4*)&xg0[u * 4];
            c0[q] = sigm_fast(xv.x) * tanh_fast(xv.z);
            float h0 = sigm_fast(xv.w) * tanh_fast(c0[q]);
            sh0[warp][u] = __uint_as_float(f2tf32(h0));
            float4 a1 = *(const float4*)&xg1[u * 4];
            ax[q] = a1.x; ay[q] = a1.y; az[q] = a1.z; aw[q] = a1.w;
        }
    }
    for (int ch = 0; ch < 8; ch++) {
        __syncthreads();
#pragma unroll
        for (int q = 0; q < 8; q++) {
            int i = tid + q * 256;
            int r = i >> 7, c4 = i & 127;
            *(float4*)&sw[r * 516 + c4 * 4] = *(const float4*)&Wt[(ch * 16 + r) * 512 + c4 * 4];
        }
        __syncthreads();
        if (active) {
#pragma unroll
            for (int kk = 0; kk < 16; kk++) {
                float hk = sh0[warp][ch * 16 + kk];
#pragma unroll
                for (int q = 0; q < 4; q++) {
                    float4 w4 = *(const float4*)&sw[kk * 516 + (lane + 32 * q) * 4];
                    ax[q] += hk * w4.x; ay[q] += hk * w4.y;
                    az[q] += hk * w4.z; aw[q] += hk * w4.w;
                }
            }
        }
    }
    if (active) {
#pragma unroll
        for (int q = 0; q < 4; q++) {
            int u = lane + 32 * q;
            float c1 = sigm_fast(ay[q]) * c0[q] + sigm_fast(ax[q]) * tanh_fast(az[q]);
            float h1 = sigm_fast(aw[q]) * tanh_fast(c1);
            float h1p = __shfl_xor_sync(~0u, h1, 1);
            if ((lane & 1) == 0)
                g_hclsN[(dir * 625 + cls) * 64 + (u >> 1)] = packbf(h1, h1p);
            g_ccls[(dir * 625 + cls) * 128 + u] = c1;
        }
    }
}

// ---------------- entity BiLSTM steps 2..7: bf16 + ldmatrix, resident Whh -------
// smem words: hp 64*68=4352 | brs 64*520=33280 | xsm 25*516=12900 | sdeg 512 | scls 64
#define HPW 0
#define BRS 4352
#define XSW 37632
#define SDG 50532
#define SCL 51044
#define ESMEM (51108 * 4)

__global__ void __launch_bounds__(512, 1) k_entity2(const int* __restrict__ degrees) {
    extern __shared__ unsigned smu[];
    unsigned* hp = smu + HPW;
    unsigned* brs = smu + BRS;
    float* xsm = (float*)(smu + XSW);
    int* sdeg = (int*)(smu + SDG);
    int* scls = (int*)(smu + SCL);

    const int tid = threadIdx.x, lane = tid & 31, wid = tid >> 5;
    const int dir = blockIdx.y;
    const int n0 = blockIdx.x * 64;
    const unsigned* Wb = g_Wb + dir * 32768;
    const float* xg = g_xgI + dir * 25 * 512;

    {
        int row = tid >> 3, t = tid & 7, n = n0 + row;
        sdeg[tid] = (n < N_) ? degrees[n * 8 + (dir ? 7 - t : t)] : 0;
    }
    for (int i = tid; i < 25 * 512; i += 512)
        xsm[(i >> 9) * 516 + (i & 511)] = xg[i];
    __syncthreads();
    if (tid < 64) scls[tid] = sdeg[tid * 8] * 25 + sdeg[tid * 8 + 1];
    __syncthreads();

    // h init (natural layout) + resident weights
    for (int i = tid; i < 64 * 64; i += 512) {
        int row = i >> 6, p = i & 63;
        hp[row * 68 + p] = g_hclsN[(dir * 625 + scls[row]) * 64 + p];
    }
#pragma unroll
    for (int q = 0; q < 16; q++) {
        int idx = tid + q * 512;
        int r = idx >> 7, c4 = idx & 127;
        *(uint4*)&brs[r * 520 + c4 * 4] = *(const uint4*)&Wb[r * 512 + c4 * 4];
    }

    const int par = lane & 1;
    float cst[16];
#pragma unroll
    for (int mf = 0; mf < 4; mf++)
#pragma unroll
        for (int nf = 0; nf < 4; nf++) {
            int row = mf * 16 + (lane >> 2) + 8 * par;
            int u = wid * 8 + nf * 2 + ((lane & 3) >> 1);
            cst[mf * 4 + nf] = g_ccls[(dir * 625 + scls[row]) * 128 + u];
        }

    // ldmatrix base addresses (bytes), per mf
    unsigned hpb = (unsigned)__cvta_generic_to_shared(hp);
    unsigned am[4];
#pragma unroll
    for (int mf = 0; mf < 4; mf++)
        am[mf] = hpb + ((mf * 16 + (lane & 15)) * 68 + ((lane >> 4) & 1) * 4) * 4;
    __syncthreads();

    for (int step = 2; step < 8; step++) {
        float acc[4][4][4];
#pragma unroll
        for (int mf = 0; mf < 4; mf++)
#pragma unroll
            for (int nf = 0; nf < 4; nf++)
#pragma unroll
                for (int q = 0; q < 4; q++) acc[mf][nf][q] = 0.f;

#pragma unroll
        for (int sub = 0; sub < 8; sub++) {
            int kro = sub * 8;
            unsigned b0[4], b1[4];
#pragma unroll
            for (int nf = 0; nf < 4; nf++) {
                int col = wid * 32 + nf * 8 + (lane >> 2);
                b0[nf] = brs[(kro + (lane & 3)) * 520 + col];
                b1[nf] = brs[(kro + 4 + (lane & 3)) * 520 + col];
            }
#pragma unroll
            for (int mf = 0; mf < 4; mf++) {
                unsigned a0, a1, a2, a3;
                ldsm4(a0, a1, a2, a3, am[mf] + sub * 32);
#pragma unroll
                for (int nf = 0; nf < 4; nf++)
                    mma16(acc[mf][nf], a0, a1, a2, a3, b0[nf], b1[nf]);
            }
        }
        __syncthreads();   // all h reads done before epilogue writes

#pragma unroll
        for (int mf = 0; mf < 4; mf++)
#pragma unroll
            for (int nf = 0; nf < 4; nf++) {
                float* a = acc[mf][nf];
                float x0 = __shfl_xor_sync(~0u, par ? a[0] : a[2], 1);
                float x1 = __shfl_xor_sync(~0u, par ? a[1] : a[3], 1);
                int row = mf * 16 + (lane >> 2) + 8 * par;
                int u = wid * 8 + nf * 2 + ((lane & 3) >> 1);
                int d = sdeg[row * 8 + step];
                float4 xv = *(const float4*)&xsm[d * 516 + u * 4];
                float iv, fv, gv, ov;
                if (par) { iv = x0; fv = x1; gv = a[2]; ov = a[3]; }
                else     { iv = a[0]; fv = a[1]; gv = x0; ov = x1; }
                iv += xv.x; fv += xv.y; gv += xv.z; ov += xv.w;
                float c = cst[mf * 4 + nf];
                c = sigm_fast(fv) * c + sigm_fast(iv) * tanh_fast(gv);
                cst[mf * 4 + nf] = c;
                float h = sigm_fast(ov) * tanh_fast(c);
                if (step < 7) {
                    float hq = __shfl_xor_sync(~0u, h, 2);
                    if ((lane & 2) == 0)
                        hp[row * 68 + wid * 4 + nf] = packbf(h, hq);
                } else {
                    int n = n0 + row;
                    if (n < N_) g_eh[n * 256 + dir * 128 + u] = h;
                }
            }
        __syncthreads();
    }
}

// ---------------- entity attention ----------------
__global__ void k_eattn(const float* __restrict__ e_lin_W, const float* __restrict__ e_lin_b) {
    __shared__ float sw[24 * 256];
    __shared__ float sb[24];
    int tid = threadIdx.x;
    for (int i = tid; i < 24 * 256; i += 256) sw[i] = e_lin_W[i];
    if (tid < 24) sb[tid] = e_lin_b[tid];
    __syncthreads();
    int lane = tid & 31;
    for (int n = blockIdx.x * 8 + (tid >> 5); n < N_; n += gridDim.x * 8) {
        float h[8];
        const float* hpx = g_eh + n * 256;
#pragma unroll
        for (int j = 0; j < 8; j++) h[j] = hpx[lane + 32 * j];
        float mine = -1e30f;
#pragma unroll
        for (int op = 0; op < 24; op++) {
            const float* wp = sw + op * 256 + lane;
            float s = 0.f;
#pragma unroll
            for (int j = 0; j < 8; j++) s += h[j] * wp[32 * j];
            for (int o = 16; o; o >>= 1) s += __shfl_xor_sync(~0u, s, o);
            if (lane == op) mine = s + sb[op];
        }
        float mx = mine;
        for (int o = 16; o; o >>= 1) mx = fmaxf(mx, __shfl_xor_sync(~0u, mx, o));
        float e = (lane < 24) ? expf(mine - mx) : 0.f;
        float sum = e;
        for (int o = 16; o; o >>= 1) sum += __shfl_xor_sync(~0u, sum, o);
        if (lane < 24) g_attn[n * 24 + lane] = e / sum;
    }
}

// ---------------- CSR build ----------------
__global__ void k_deg(const int* __restrict__ t_heads, const int* __restrict__ t_tails) {
    int e = blockIdx.x * blockDim.x + threadIdx.x;
    if (e < E_) {
        atomicAdd(&g_deg[t_tails[e]], 1);
        atomicAdd(&g_deg[t_heads[e]], 1);
    }
}

__global__ void k_scan() {
    __shared__ int part[1024];
    int tid = threadIdx.x;
    int s = tid * 49, e = min(s + 49, N_);
    int sum = 0;
    for (int i = s; i < e; i++) sum += g_deg[i];
    part[tid] = sum;
    __syncthreads();
    for (int off = 1; off < 1024; off <<= 1) {
        int v = (tid >= off) ? part[tid - off] : 0;
        __syncthreads();
        part[tid] += v;
        __syncthreads();
    }
    int run = tid ? part[tid - 1] : 0;
    for (int i = s; i < e; i++) {
        g_rowptr[i] = run;
        g_cursor[i] = run;
        run += g_deg[i];
    }
    if (tid == 1023) g_rowptr[N_] = part[1023];
}

__global__ void k_fill(const int* __restrict__ rels, const int* __restrict__ t_heads,
                       const int* __restrict__ t_tails) {
    int e = blockIdx.x * blockDim.x + threadIdx.x;
    if (e >= E_) return;
    int rel = rels[e], hd = t_heads[e], tl = t_tails[e];
    int wb = __float_as_int(g_attn[hd * OPS_ + rel]);
    int p1 = atomicAdd(&g_cursor[tl], 1);
    g_csr2[p1] = make_int2((hd << 5) | rel, wb);
    int p2 = atomicAdd(&g_cursor[hd], 1);
    g_csr2[p2] = make_int2((tl << 5) | (rel + 12), wb);
}

// ---------------- query path ----------------
__global__ void k_qtr(const float* __restrict__ qWih, const float* __restrict__ qWhh) {
    __shared__ float t[32][33];
    int m = blockIdx.z;
    const float* src = (m < 6) ? qWih + m * 512 * 128 : qWhh + (m - 6) * 512 * 128;
    float* dst = (m < 6) ? g_qWihT + m * 128 * 512 : g_qWhhT + (m - 6) * 128 * 512;
    int r0 = blockIdx.x * 32, k0 = blockIdx.y * 32;
    int tx = threadIdx.x, ty = threadIdx.y;
#pragma unroll
    for (int j = 0; j < 32; j += 8) t[ty + j][tx] = src[(r0 + ty + j) * 128 + k0 + tx];
    __syncthreads();
#pragma unroll
    for (int j = 0; j < 32; j += 8) dst[(k0 + ty + j) * 512 + r0 + tx] = t[tx][ty + j];
}

__global__ void __launch_bounds__(512) k_qlstm2(const int* __restrict__ queries,
                                                const float* __restrict__ q_emb,
                                                const float* __restrict__ q_bih,
                                                const float* __restrict__ q_bhh) {
    __shared__ float xs[8][128];
    __shared__ float hs[8][128];
    __shared__ float gsm[8][512];
    int tid = threadIdx.x;
    int rd = blockIdx.x >> 2, bg = blockIdx.x & 3, b0 = bg * 8;
    for (int i = tid; i < 1024; i += 512) {
        int b = i >> 7, k = i & 127;
        xs[b][k] = q_emb[queries[b0 + b] * 128 + k];
        hs[b][k] = 0.f;
    }
    __syncthreads();
    const float* WihT = g_qWihT + rd * 65536;
    const float* WhhT = g_qWhhT + rd * 65536;
    float bias = q_bih[rd * 512 + tid] + q_bhh[rd * 512 + tid];
    float xw[8];
#pragma unroll
    for (int b = 0; b < 8; b++) xw[b] = bias;
    for (int k = 0; k < 128; k++) {
        float w = WihT[k * 512 + tid];
#pragma unroll
        for (int b = 0; b < 8; b++) xw[b] += xs[b][k] * w;
    }
    float c2[2] = {0.f, 0.f};
    int j = tid & 127, bb0 = (tid >> 7) * 2;
    for (int t = 0; t < 3; t++) {
        float acc[8];
#pragma unroll
        for (int b = 0; b < 8; b++) acc[b] = xw[b];
        for (int k = 0; k < 128; k++) {
            float w = WhhT[k * 512 + tid];
#pragma unroll
            for (int b = 0; b < 8; b++) acc[b] += hs[b][k] * w;
        }
#pragma unroll
        for (int b = 0; b < 8; b++) gsm[b][tid] = acc[b];
        __syncthreads();
#pragma unroll
        for (int e = 0; e < 2; e++) {
            int b = bb0 + e;
            float iv = gsm[b][j], fv = gsm[b][128 + j];
            float gv = gsm[b][256 + j], ov = gsm[b][384 + j];
            c2[e] = sigm(fv) * c2[e] + sigm(iv) * tanhf(gv);
            float h = sigm(ov) * tanhf(c2[e]);
            hs[b][j] = h;
            g_qys[((rd * 3 + t) * B_ + b0 + b) * H_ + j] = h;
        }
        __syncthreads();
    }
}

__global__ void k_qattn(const float* __restrict__ q_lin_W, const float* __restrict__ q_lin_b) {
    int w = (blockIdx.x * blockDim.x + threadIdx.x) >> 5;
    int lane = threadIdx.x & 31;
    if (w >= R_ * T_ * B_) return;
    int b = w & 31, t = (w >> 5) % 3, r = w / 96;
    const float* ysf = g_qys + (((r * 2 + 0) * 3 + t) * B_ + b) * H_;
    const float* ysb = g_qys + (((r * 2 + 1) * 3 + (2 - t)) * B_ + b) * H_;
    float s = -1e30f;
    if (lane <= OPS_) {
        s = q_lin_b[lane];
        const float* wv = q_lin_W + lane * 256;
        for (int k = 0; k < 128; k++) s += ysf[k] * wv[k];
        for (int k = 0; k < 128; k++) s += ysb[k] * wv[128 + k];
    }
    float mx = s;
    for (int o = 16; o; o >>= 1) mx = fmaxf(mx, __shfl_xor_sync(~0u, mx, o));
    float e = (lane <= OPS_) ? expf(s - mx) : 0.f;
    float sum = e;
    for (int o = 16; o; o >>= 1) sum += __shfl_xor_sync(~0u, sum, o);
    if (lane <= OPS_) g_qaT[((r * 3 + t) * (OPS_ + 1) + lane) * B_ + b] = e / sum;
}

// ---------------- t=0 propagation ----------------
__global__ void k_prop0(float* __restrict__ memout, const int* __restrict__ heads, int rt) {
    __shared__ float qs[25 * 32];
    int tid = threadIdx.x, lane = tid & 31, wrp = tid >> 5;
    const float* qsrc = g_qaT + rt * 25 * 32;
    for (int i = tid; i < 800; i += 1024) qs[i] = qsrc[i];
    __syncthreads();
    int b = wrp;
    int hb = heads[b];
    float q24 = qs[24 * 32 + b];
    int p0 = g_rowptr[hb], p1 = g_rowptr[hb + 1];
    float lsum = 0.f;
    for (int p = p0 + lane; p < p1; p += 32) {
        int2 e = g_csr2[p];
        int s = e.x >> 5, idx = e.x & 31;
        int qi = (idx < 12) ? (idx + 12) : (idx - 12);
        float v = qs[qi * 32 + b] * __int_as_float(e.y);
        atomicAdd(&memout[s * 32 + b], v);
        lsum += v;
    }
    for (int o = 16; o; o >>= 1) lsum += __shfl_xor_sync(~0u, lsum, o);
    if (lane == 0) {
        atomicAdd(&memout[hb * 32 + b], q24);
        atomicAdd(&g_sums[rt * 32 + b], lsum + q24);
    }
}

// ---------------- t>0 propagation ----------------
__global__ void __launch_bounds__(256, 6) k_prop(const float* __restrict__ memin,
                                                 float* __restrict__ memout,
                                                 int rt, int rtprev) {
    __shared__ float qs[25 * 32];
    __shared__ float red[8][32];
    int tid = threadIdx.x, lane = tid & 31, wrp = tid >> 5;
    const float* qsrc = g_qaT + rt * 25 * 32;
    for (int i = tid; i < 800; i += 256) qs[i] = qsrc[i];
    __syncthreads();

    float sp = 1.f / fmaxf(1e-20f, g_sums[rtprev * 32 + lane]);
    float q24 = qs[24 * 32 + lane];

    float lsum = 0.f;
    int nwarps = (gridDim.x * blockDim.x) >> 5;
    for (int n = (blockIdx.x * blockDim.x + tid) >> 5; n < N_; n += nwarps) {
        int p0 = g_rowptr[n], p1 = g_rowptr[n + 1];
        float acc = memin[n * 32 + lane] * q24;
        int nfull = (p1 - p0) & ~3;
        int pend = p0 + nfull;
        int p = p0;
        int2 ee[4];
        if (p < pend) {
#pragma unroll
            for (int j = 0; j < 4; j++) ee[j] = g_csr2[p + j];
        }
        while (p < pend) {
            float mm[4];
#pragma unroll
            for (int j = 0; j < 4; j++) mm[j] = memin[(ee[j].x >> 5) * 32 + lane];
            int2 en[4];
            if (p + 4 < pend) {
#pragma unroll
                for (int j = 0; j < 4; j++) en[j] = g_csr2[p + 4 + j];
            }
#pragma unroll
            for (int j = 0; j < 4; j++)
                acc += qs[(ee[j].x & 31) * 32 + lane] * __int_as_float(ee[j].y) * mm[j];
#pragma unroll
            for (int j = 0; j < 4; j++) ee[j] = en[j];
            p += 4;
        }
        for (; p < p1; p++) {
            int2 e = g_csr2[p];
            acc += qs[(e.x & 31) * 32 + lane] * __int_as_float(e.y) *
                   memin[(e.x >> 5) * 32 + lane];
        }
        acc *= sp;
        memout[n * 32 + lane] = acc;
        lsum += acc;
    }
    red[wrp][lane] = lsum;
    __syncthreads();
    if (wrp == 0) {
        float s = 0.f;
#pragma unroll
        for (int q = 0; q < 8; q++) s += red[q][lane];
        atomicAdd(&g_sums[rt * 32 + lane], s);
    }
}

// ---------------- transposed accumulate ----------------
__global__ void k_accum(const float* __restrict__ memlast, float* __restrict__ out, int rtl) {
    __shared__ float t[32][33];
    int n0 = blockIdx.x * 32;
    int tx = threadIdx.x & 31, ty = threadIdx.x >> 5;
#pragma unroll
    for (int j = 0; j < 32; j += 8) {
        int n = n0 + ty + j;
        if (n < N_) t[ty + j][tx] = memlast[n * 32 + tx];
    }
    __syncthreads();
    int n = n0 + tx;
    if (n < N_) {
#pragma unroll
        for (int j = 0; j < 32; j += 8) {
            int b = ty + j;
            float inv = 1.f / fmaxf(1e-20f, g_sums[rtl * 32 + b]);
            out[b * N_ + n] += t[tx][b] * inv;
        }
    }
}

// ---------------- host ----------------
extern "C" void kernel_launch(void* const* d_in, const int* in_sizes, int n_in,
                              void* d_out, int out_size) {
    const int* queries   = (const int*)d_in[0];
    const int* heads     = (const int*)d_in[1];
    const int* rels      = (const int*)d_in[2];
    const int* t_heads   = (const int*)d_in[3];
    const int* t_tails   = (const int*)d_in[4];
    const int* degrees   = (const int*)d_in[5];
    const float* q_emb   = (const float*)d_in[6];
    const float* ent_emb = (const float*)d_in[7];
    const float* q_Wih   = (const float*)d_in[8];
    const float* q_Whh   = (const float*)d_in[9];
    const float* q_bih   = (const float*)d_in[10];
    const float* q_bhh   = (const float*)d_in[11];
    const float* e_Wih   = (const float*)d_in[12];
    const float* e_Whh   = (const float*)d_in[13];
    const float* e_bih   = (const float*)d_in[14];
    const float* e_bhh   = (const float*)d_in[15];
    const float* q_lin_W = (const float*)d_in[16];
    const float* q_lin_b = (const float*)d_in[17];
    const float* e_lin_W = (const float*)d_in[18];
    const float* e_lin_b = (const float*)d_in[19];
    float* out = (float*)d_out;

    void *p_sums, *p_deg, *p_memA, *p_memB;
    cudaGetSymbolAddress(&p_sums, g_sums);
    cudaGetSymbolAddress(&p_deg, g_deg);
    cudaGetSymbolAddress(&p_memA, g_memA);
    cudaGetSymbolAddress(&p_memB, g_memB);
    float* memA = (float*)p_memA;
    float* memB = (float*)p_memB;

    cudaMemsetAsync(d_out, 0, (size_t)N_ * B_ * sizeof(float));
    cudaMemsetAsync(p_sums, 0, R_ * T_ * B_ * sizeof(float));
    cudaMemsetAsync(p_deg, 0, N_ * sizeof(int));

    // kernels 1..3, then k_entity2 as the 4th kernel launch (ncu capture slot)
    k_xg<<<dim3(25, 2), 512>>>(ent_emb, e_Wih, e_bih, e_bhh);
    k_whhT<<<dim3(128, 2), 512>>>(e_Whh);
    k_cls<<<dim3(79, 2), 256>>>();

    cudaFuncSetAttribute(k_entity2, cudaFuncAttributeMaxDynamicSharedMemorySize, ESMEM);
    k_entity2<<<dim3((N_ + 63) / 64, 2), 512, ESMEM>>>(degrees);

    k_qtr<<<dim3(16, 4, 12), dim3(32, 8)>>>(q_Wih, q_Whh);
    k_deg<<<(E_ + 255) / 256, 256>>>(t_heads, t_tails);
    k_scan<<<1, 1024>>>();
    k_eattn<<<782, 256>>>(e_lin_W, e_lin_b);
    k_fill<<<(E_ + 255) / 256, 256>>>(rels, t_heads, t_tails);

    k_qlstm2<<<24, 512>>>(queries, q_emb, q_bih, q_bhh);
    k_qattn<<<36, 256>>>(q_lin_W, q_lin_b);

    for (int r = 0; r < R_; r++) {
        int rt0 = r * 3;
        cudaMemsetAsync(p_memB, 0, (size_t)N_ * B_ * sizeof(float));
        k_prop0<<<1, 1024>>>(memB, heads, rt0);
        k_prop<<<1480, 256>>>(memB, memA, rt0 + 1, rt0);
        k_prop<<<1480, 256>>>(memA, memB, rt0 + 2, rt0 + 1);
        k_accum<<<(N_ + 31) / 32, 256>>>(memB, out, rt0 + 2);
    }
}